// round 12
// baseline (speedup 1.0000x reference)
#include <cuda_runtime.h>
#include <cstdint>

// Problem dimensions (fixed by the reference).
#define NW 50000
#define NT 2000
#define ND 50000
#define DO 128
#define DW 256
#define E_MAX 2200000   // total edges = 2.1M; padded

// Concatenated per-(relation,dst) counter layout.
constexpr int DEG_WW = 0;
constexpr int DEG_WT = NW;
constexpr int DEG_TT = NW + NT;
constexpr int DEG_WD = NW + 2 * NT;
constexpr int DEG_TD = NW + 2 * NT + ND;
constexpr int NDEG   = NW + 2 * NT + 2 * ND;   // 154000
constexpr int NSCAN  = (NDEG + 1023) / 1024;   // 151 scan blocks

// ---------------------------------------------------------------------------
// Scratch (static __device__ arrays — allocation-free per harness rules).
// ---------------------------------------------------------------------------
__device__ float g_Wh_ww[(size_t)NW * DO];
__device__ float g_Wh_wt[(size_t)NW * DO];
__device__ float g_Wh_wd[(size_t)NW * DO];
__device__ float g_Wh_td[(size_t)NT * DO];
__device__ float g_Wh_tt[(size_t)NT * DO];

__device__ int      g_cnt[NDEG];    // per-(rel,dst) degree
__device__ int      g_cur[NDEG];    // fill cursors for permute
__device__ int      g_off[NDEG];    // exclusive scan of g_cnt (global)
__device__ int      g_bsum[256];    // scan block sums
__device__ int      g_boff[256];    // scanned block sums

__device__ unsigned long long g_edge[E_MAX];  // packed (src | w<<32), dst-grouped

// Edge-set bundle for merged CSR kernels (passed by value).
struct ES {
    const int*   src[5];
    const int*   dst[5];
    const float* w[5];
    int          E[5];
    int          base[5];
};

// ---------------------------------------------------------------------------
// CSR build: zero counters -> merged histogram -> 3-phase scan -> merged
// permute (packed 8-byte edge payloads).
// ---------------------------------------------------------------------------
__global__ void zero_cnt() {
    int i = blockIdx.x * blockDim.x + threadIdx.x;
    if (i < NDEG) { g_cnt[i] = 0; g_cur[i] = 0; }
}

__global__ __launch_bounds__(256)
void hist_all(ES es, int total) {
    int i = blockIdx.x * blockDim.x + threadIdx.x;
    if (i >= total) return;
    int e = i;
#pragma unroll
    for (int r = 0; r < 5; r++) {
        if (e < es.E[r]) {
            atomicAdd(&g_cnt[es.base[r] + es.dst[r][e]], 1);
            return;
        }
        e -= es.E[r];
    }
}

__global__ __launch_bounds__(256)
void scan1() {
    __shared__ int sh[256];
    int t    = threadIdx.x;
    int base = blockIdx.x * 1024 + t * 4;
    int v[4];
#pragma unroll
    for (int j = 0; j < 4; j++)
        v[j] = (base + j < NDEG) ? g_cnt[base + j] : 0;
    int tsum = v[0] + v[1] + v[2] + v[3];
    sh[t] = tsum;
    __syncthreads();
    for (int d = 1; d < 256; d <<= 1) {
        int x = (t >= d) ? sh[t - d] : 0;
        __syncthreads();
        sh[t] += x;
        __syncthreads();
    }
    int run = sh[t] - tsum;
#pragma unroll
    for (int j = 0; j < 4; j++) {
        if (base + j < NDEG) g_off[base + j] = run;
        run += v[j];
    }
    if (t == 255) g_bsum[blockIdx.x] = sh[255];
}

__global__ __launch_bounds__(256)
void scan2() {
    __shared__ int sh[256];
    int t = threadIdx.x;
    int v = (t < NSCAN) ? g_bsum[t] : 0;
    sh[t] = v;
    __syncthreads();
    for (int d = 1; d < 256; d <<= 1) {
        int x = (t >= d) ? sh[t - d] : 0;
        __syncthreads();
        sh[t] += x;
        __syncthreads();
    }
    g_boff[t] = sh[t] - v;
}

__global__ __launch_bounds__(256)
void scan3() {
    int i = blockIdx.x * blockDim.x + threadIdx.x;
    if (i < NDEG) g_off[i] += g_boff[i >> 10];
}

__global__ __launch_bounds__(256)
void permute_all(ES es, int total) {
    int i = blockIdx.x * blockDim.x + threadIdx.x;
    if (i >= total) return;
    int e = i;
#pragma unroll
    for (int r = 0; r < 5; r++) {
        if (e < es.E[r]) {
            int d   = es.base[r] + es.dst[r][e];
            int pos = g_off[d] + atomicAdd(&g_cur[d], 1);
            unsigned long long p =
                (unsigned long long)(unsigned)es.src[r][e] |
                ((unsigned long long)__float_as_uint(es.w[r][e]) << 32);
            g_edge[pos] = p;
            return;
        }
        e -= es.E[r];
    }
}

// ---------------------------------------------------------------------------
// Split-TF32 tensor-core GEMM + bias: C[M x 128] = A[M x DIN] @ W[DIN x 128]+b
// mma.sync.m16n8k8.tf32 with 2-term error compensation (fp32-grade accuracy).
// BM=128, BN=128, BK=16, 256 threads = 8 warps (4 along M x 2 along N).
// Register double-buffered mainloop: next tiles are prefetched into registers
// right after the fill barrier so LDG latency overlaps the 48 mma ops.
// blockIdx.y selects one of three (W, b, C) sets -> all 3 word GEMMs in ONE
// launch (1173 CTAs = near-perfect wave packing).
// ---------------------------------------------------------------------------
__device__ __forceinline__ uint32_t f2tf32(float x) {
    uint32_t r;
    asm("cvt.rna.tf32.f32 %0, %1;" : "=r"(r) : "f"(x));
    return r;
}

__device__ __forceinline__ void mma_tf32(float* d, const uint32_t* a,
                                         const uint32_t* b) {
    asm volatile(
        "mma.sync.aligned.m16n8k8.row.col.f32.tf32.tf32.f32 "
        "{%0,%1,%2,%3}, {%4,%5,%6,%7}, {%8,%9}, {%0,%1,%2,%3};"
        : "+f"(d[0]), "+f"(d[1]), "+f"(d[2]), "+f"(d[3])
        : "r"(a[0]), "r"(a[1]), "r"(a[2]), "r"(a[3]), "r"(b[0]), "r"(b[1]));
}

template <int DIN>
__global__ __launch_bounds__(256)
void gemm_tf32(const float* __restrict__ A,
               const float* __restrict__ W0, const float* __restrict__ b0,
               float* __restrict__ C0,
               const float* __restrict__ W1, const float* __restrict__ b1,
               float* __restrict__ C1,
               const float* __restrict__ W2, const float* __restrict__ b2,
               float* __restrict__ C2, int M) {
    constexpr int AS = 20;    // As row stride (16 + 4 pad)
    constexpr int BS = 136;   // Bs row stride (128 + 8 pad)
    __shared__ float As_hi[128 * AS], As_lo[128 * AS];
    __shared__ float Bs_hi[16 * BS],  Bs_lo[16 * BS];

    const float* W    = (blockIdx.y == 0) ? W0 : (blockIdx.y == 1) ? W1 : W2;
    const float* bias = (blockIdx.y == 0) ? b0 : (blockIdx.y == 1) ? b1 : b2;
    float*       C    = (blockIdx.y == 0) ? C0 : (blockIdx.y == 1) ? C1 : C2;

    const int t    = threadIdx.x;
    const int m0   = blockIdx.x * 128;
    const int wid  = t >> 5;
    const int lane = t & 31;
    const int g    = lane >> 2;   // group id  (0..7)
    const int tg   = lane & 3;    // thread-in-group (0..3)
    const int m0w  = (wid & 3) * 32;   // warp M origin
    const int n0w  = (wid >> 2) * 64;  // warp N origin

    // Fill coordinates.
    const int ar = t >> 1;           // A row 0..127
    const int ak = (t & 1) * 8;      // A k offset 0/8
    const int br = t >> 4;           // B k row 0..15
    const int bn = (t & 15) * 8;     // B n offset 0..120

    float acc[2][8][4];
#pragma unroll
    for (int mt = 0; mt < 2; mt++)
#pragma unroll
        for (int nt = 0; nt < 8; nt++)
#pragma unroll
            for (int j = 0; j < 4; j++) acc[mt][nt][j] = 0.0f;

    float va[8], vb[8];
    // Prologue: load tile 0 into registers.
    {
        if (m0 + ar < M) {
            const float* src = A + (size_t)(m0 + ar) * DIN + ak;
            *(float4*)(va)     = *(const float4*)(src);
            *(float4*)(va + 4) = *(const float4*)(src + 4);
        } else {
#pragma unroll
            for (int j = 0; j < 8; j++) va[j] = 0.0f;
        }
        const float* srcB = W + (size_t)br * DO + bn;
        *(float4*)(vb)     = *(const float4*)(srcB);
        *(float4*)(vb + 4) = *(const float4*)(srcB + 4);
    }

    for (int k0 = 0; k0 < DIN; k0 += 16) {
        // ---- Store + split-convert current registers into smem. ----
#pragma unroll
        for (int j = 0; j < 8; j++) {
            uint32_t hi = f2tf32(va[j]);
            float hif   = __uint_as_float(hi);
            uint32_t lo = f2tf32(va[j] - hif);
            As_hi[ar * AS + ak + j] = hif;
            As_lo[ar * AS + ak + j] = __uint_as_float(lo);
        }
#pragma unroll
        for (int j = 0; j < 8; j++) {
            uint32_t hi = f2tf32(vb[j]);
            float hif   = __uint_as_float(hi);
            uint32_t lo = f2tf32(vb[j] - hif);
            Bs_hi[br * BS + bn + j] = hif;
            Bs_lo[br * BS + bn + j] = __uint_as_float(lo);
        }
        __syncthreads();

        // ---- Prefetch next tile into registers (overlaps the mma below). ----
        if (k0 + 16 < DIN) {
            if (m0 + ar < M) {
                const float* src = A + (size_t)(m0 + ar) * DIN + k0 + 16 + ak;
                *(float4*)(va)     = *(const float4*)(src);
                *(float4*)(va + 4) = *(const float4*)(src + 4);
            } else {
#pragma unroll
                for (int j = 0; j < 8; j++) va[j] = 0.0f;
            }
            const float* srcB = W + (size_t)(k0 + 16 + br) * DO + bn;
            *(float4*)(vb)     = *(const float4*)(srcB);
            *(float4*)(vb + 4) = *(const float4*)(srcB + 4);
        }

        // ---- MMA over the smem tile. ----
#pragma unroll
        for (int ks = 0; ks < 2; ks++) {
            const int k = ks * 8;
            uint32_t a_hi[2][4], a_lo[2][4];
#pragma unroll
            for (int mt = 0; mt < 2; mt++) {
                int mr = m0w + mt * 16;
                int i0 = (mr + g) * AS + k + tg;
                int i1 = (mr + g + 8) * AS + k + tg;
                a_hi[mt][0] = __float_as_uint(As_hi[i0]);
                a_hi[mt][1] = __float_as_uint(As_hi[i1]);
                a_hi[mt][2] = __float_as_uint(As_hi[i0 + 4]);
                a_hi[mt][3] = __float_as_uint(As_hi[i1 + 4]);
                a_lo[mt][0] = __float_as_uint(As_lo[i0]);
                a_lo[mt][1] = __float_as_uint(As_lo[i1]);
                a_lo[mt][2] = __float_as_uint(As_lo[i0 + 4]);
                a_lo[mt][3] = __float_as_uint(As_lo[i1 + 4]);
            }
#pragma unroll
            for (int nt = 0; nt < 8; nt++) {
                int nb = n0w + nt * 8 + g;
                int j0 = (k + tg) * BS + nb;
                int j1 = (k + tg + 4) * BS + nb;
                uint32_t b_hi[2], b_lo[2];
                b_hi[0] = __float_as_uint(Bs_hi[j0]);
                b_hi[1] = __float_as_uint(Bs_hi[j1]);
                b_lo[0] = __float_as_uint(Bs_lo[j0]);
                b_lo[1] = __float_as_uint(Bs_lo[j1]);
#pragma unroll
                for (int mt = 0; mt < 2; mt++) {
                    mma_tf32(acc[mt][nt], a_hi[mt], b_hi);
                    mma_tf32(acc[mt][nt], a_lo[mt], b_hi);
                    mma_tf32(acc[mt][nt], a_hi[mt], b_lo);
                }
            }
        }
        __syncthreads();
    }

    // Epilogue: bias + store.
#pragma unroll
    for (int nt = 0; nt < 8; nt++) {
        int col = n0w + nt * 8 + 2 * tg;
        float bx = bias[col];
        float by = bias[col + 1];
#pragma unroll
        for (int mt = 0; mt < 2; mt++) {
            int mr = m0 + m0w + mt * 16 + g;
            if (mr < M) {
                float2 o = make_float2(acc[mt][nt][0] + bx,
                                       acc[mt][nt][1] + by);
                *(float2*)(C + (size_t)mr * DO + col) = o;
            }
            if (mr + 8 < M) {
                float2 o = make_float2(acc[mt][nt][2] + bx,
                                       acc[mt][nt][3] + by);
                *(float2*)(C + (size_t)(mr + 8) * DO + col) = o;
            }
        }
    }
}

// ---------------------------------------------------------------------------
// Aggregation (CSR, atomic-free): ONE WARP per dst row, lane owns a float4.
// 4x-unrolled edge loop keeps 4 row-gathers in flight per warp; __ldg for all
// read-only traffic. Mean + cross-etype sum + coalesced output store fused.
// ---------------------------------------------------------------------------
__device__ __forceinline__ float4 mean_row_w(const float* __restrict__ Wh,
                                             int cnt_base, int row, int lane) {
    int beg = g_off[cnt_base + row];
    int deg = g_cnt[cnt_base + row];
    float4 a0 = make_float4(0.f, 0.f, 0.f, 0.f);
    float4 a1 = make_float4(0.f, 0.f, 0.f, 0.f);
    float4 a2 = make_float4(0.f, 0.f, 0.f, 0.f);
    float4 a3 = make_float4(0.f, 0.f, 0.f, 0.f);
    int e = 0;
    for (; e + 4 <= deg; e += 4) {
        unsigned long long pA = __ldg(&g_edge[beg + e]);
        unsigned long long pB = __ldg(&g_edge[beg + e + 1]);
        unsigned long long pC = __ldg(&g_edge[beg + e + 2]);
        unsigned long long pD = __ldg(&g_edge[beg + e + 3]);
        float4 vA = __ldg((const float4*)(Wh + (size_t)(unsigned)pA * DO) + lane);
        float4 vB = __ldg((const float4*)(Wh + (size_t)(unsigned)pB * DO) + lane);
        float4 vC = __ldg((const float4*)(Wh + (size_t)(unsigned)pC * DO) + lane);
        float4 vD = __ldg((const float4*)(Wh + (size_t)(unsigned)pD * DO) + lane);
        float wA = __uint_as_float((unsigned)(pA >> 32));
        float wB = __uint_as_float((unsigned)(pB >> 32));
        float wC = __uint_as_float((unsigned)(pC >> 32));
        float wD = __uint_as_float((unsigned)(pD >> 32));
        a0.x += wA * vA.x; a0.y += wA * vA.y; a0.z += wA * vA.z; a0.w += wA * vA.w;
        a1.x += wB * vB.x; a1.y += wB * vB.y; a1.z += wB * vB.z; a1.w += wB * vB.w;
        a2.x += wC * vC.x; a2.y += wC * vC.y; a2.z += wC * vC.z; a2.w += wC * vC.w;
        a3.x += wD * vD.x; a3.y += wD * vD.y; a3.z += wD * vD.z; a3.w += wD * vD.w;
    }
    for (; e < deg; e++) {
        unsigned long long p = __ldg(&g_edge[beg + e]);
        float w  = __uint_as_float((unsigned)(p >> 32));
        float4 v = __ldg((const float4*)(Wh + (size_t)(unsigned)p * DO) + lane);
        a0.x += w * v.x; a0.y += w * v.y; a0.z += w * v.z; a0.w += w * v.w;
    }
    float inv = (deg > 0) ? 1.0f / (float)deg : 0.0f;
    return make_float4((a0.x + a1.x + a2.x + a3.x) * inv,
                       (a0.y + a1.y + a2.y + a3.y) * inv,
                       (a0.z + a1.z + a2.z + a3.z) * inv,
                       (a0.w + a1.w + a2.w + a3.w) * inv);
}

__global__ __launch_bounds__(256)
void agg1(const float* __restrict__ Wh, int cnt_base, int out_row0,
          float* __restrict__ out, int nrows) {
    int row  = blockIdx.x * 8 + (threadIdx.x >> 5);
    int lane = threadIdx.x & 31;
    if (row >= nrows) return;
    float4 r = mean_row_w(Wh, cnt_base, row, lane);
    *(float4*)(out + (size_t)(out_row0 + row) * DO + lane * 4) = r;
}

__global__ __launch_bounds__(256)
void agg2(const float* __restrict__ WhA, int baseA,
          const float* __restrict__ WhB, int baseB, int out_row0,
          float* __restrict__ out, int nrows) {
    int row  = blockIdx.x * 8 + (threadIdx.x >> 5);
    int lane = threadIdx.x & 31;
    if (row >= nrows) return;
    float4 rA = mean_row_w(WhA, baseA, row, lane);
    float4 rB = mean_row_w(WhB, baseB, row, lane);
    float4 o  = make_float4(rA.x + rB.x, rA.y + rB.y,
                            rA.z + rB.z, rA.w + rB.w);
    *(float4*)(out + (size_t)(out_row0 + row) * DO + lane * 4) = o;
}

// ---------------------------------------------------------------------------
// Host entry.
// Input order (metadata): 0 feat_word, 1 feat_topic,
//   2-4 ww(src,dst,w), 5-7 wt, 8-10 wd, 11-13 td, 14-16 tt,
//   17/18 W_ww/b_ww, 19/20 W_wt/b_wt, 21/22 W_wd/b_wd, 23/24 W_td/b_td,
//   25/26 W_tt/b_tt
//
// DAG (capture-legal fork), R10 topology (single y=3 word GEMM = best wave
// packing), with R11's per-kernel improvements kept:
//   legacy: evFork -> G_words(y=3, evGw) -> G_topics(y=2, evGt)
//           -> [evCSR] agg_doc -> [evS2] join
//   s2:     [evFork] zero_cnt -> hist_all -> scan x3 -> permute_all (evCSR)
//           -> [evGw] agg_word -> [evGt] agg_topic (evS2)
// ---------------------------------------------------------------------------
extern "C" void kernel_launch(void* const* d_in, const int* in_sizes, int n_in,
                              void* d_out, int out_size) {
    static cudaStream_t s2 = nullptr;
    static cudaEvent_t  evFork, evCSR, evGw, evGt, evS2;
    if (s2 == nullptr) {
        cudaStreamCreateWithFlags(&s2, cudaStreamNonBlocking);
        cudaEventCreateWithFlags(&evFork, cudaEventDisableTiming);
        cudaEventCreateWithFlags(&evCSR,  cudaEventDisableTiming);
        cudaEventCreateWithFlags(&evGw,   cudaEventDisableTiming);
        cudaEventCreateWithFlags(&evGt,   cudaEventDisableTiming);
        cudaEventCreateWithFlags(&evS2,   cudaEventDisableTiming);
    }

    const float* feat_word  = (const float*)d_in[0];
    const float* feat_topic = (const float*)d_in[1];

    // Edge sets in CSR order: ww, wt, tt, wd, td.
    ES es;
    es.src[0] = (const int*)d_in[2];  es.dst[0] = (const int*)d_in[3];
    es.w[0] = (const float*)d_in[4];  es.E[0] = in_sizes[2];  es.base[0] = DEG_WW;
    es.src[1] = (const int*)d_in[5];  es.dst[1] = (const int*)d_in[6];
    es.w[1] = (const float*)d_in[7];  es.E[1] = in_sizes[5];  es.base[1] = DEG_WT;
    es.src[2] = (const int*)d_in[14]; es.dst[2] = (const int*)d_in[15];
    es.w[2] = (const float*)d_in[16]; es.E[2] = in_sizes[14]; es.base[2] = DEG_TT;
    es.src[3] = (const int*)d_in[8];  es.dst[3] = (const int*)d_in[9];
    es.w[3] = (const float*)d_in[10]; es.E[3] = in_sizes[8];  es.base[3] = DEG_WD;
    es.src[4] = (const int*)d_in[11]; es.dst[4] = (const int*)d_in[12];
    es.w[4] = (const float*)d_in[13]; es.E[4] = in_sizes[11]; es.base[4] = DEG_TD;
    int totalE = es.E[0] + es.E[1] + es.E[2] + es.E[3] + es.E[4];

    const float* W_ww = (const float*)d_in[17]; const float* b_ww = (const float*)d_in[18];
    const float* W_wt = (const float*)d_in[19]; const float* b_wt = (const float*)d_in[20];
    const float* W_wd = (const float*)d_in[21]; const float* b_wd = (const float*)d_in[22];
    const float* W_td = (const float*)d_in[23]; const float* b_td = (const float*)d_in[24];
    const float* W_tt = (const float*)d_in[25]; const float* b_tt = (const float*)d_in[26];

    float* out = (float*)d_out;

    float* p_ww; cudaGetSymbolAddress((void**)&p_ww, g_Wh_ww);
    float* p_wt; cudaGetSymbolAddress((void**)&p_wt, g_Wh_wt);
    float* p_wd; cudaGetSymbolAddress((void**)&p_wd, g_Wh_wd);
    float* p_td; cudaGetSymbolAddress((void**)&p_td, g_Wh_td);
    float* p_tt; cudaGetSymbolAddress((void**)&p_tt, g_Wh_tt);

    // ---- Fork s2 from the capture (legacy) stream. ----
    cudaEventRecord(evFork, 0);
    cudaStreamWaitEvent(s2, evFork, 0);

    // ---- s2: CSR build (independent of GEMMs). ----
    zero_cnt<<<(NDEG + 255) / 256, 256, 0, s2>>>();
    hist_all<<<(totalE + 255) / 256, 256, 0, s2>>>(es, totalE);
    scan1<<<NSCAN, 256, 0, s2>>>();
    scan2<<<1, 256, 0, s2>>>();
    scan3<<<(NDEG + 255) / 256, 256, 0, s2>>>();
    permute_all<<<(totalE + 255) / 256, 256, 0, s2>>>(es, totalE);
    cudaEventRecord(evCSR, s2);

    // ---- legacy: projections (tensor cores, split-tf32). ----
    {
        int gw = (NW + 127) / 128;   // 391 -> y=3: 1173 CTAs, ~4 full waves
        gemm_tf32<DW><<<dim3(gw, 3), 256>>>(feat_word,
                                            W_ww, b_ww, p_ww,
                                            W_wt, b_wt, p_wt,
                                            W_wd, b_wd, p_wd, NW);
        cudaEventRecord(evGw, 0);
        int gt = (NT + 127) / 128;   // 16
        gemm_tf32<128><<<dim3(gt, 2), 256>>>(feat_topic,
                                             W_tt, b_tt, p_tt,
                                             W_td, b_td, p_td,
                                             W_td, b_td, p_td, NT);
        cudaEventRecord(evGt, 0);
    }

    // ---- s2: aggregates as dependencies resolve (CSR is in-stream). ----
    cudaStreamWaitEvent(s2, evGw, 0);
    agg1<<<(NW + 7) / 8, 256, 0, s2>>>(p_ww, DEG_WW, 0, out, NW);
    cudaStreamWaitEvent(s2, evGt, 0);
    agg2<<<(NT + 7) / 8, 256, 0, s2>>>(p_wt, DEG_WT, p_tt, DEG_TT, NW, out, NT);
    cudaEventRecord(evS2, s2);

    // ---- legacy: doc aggregate (GEMMs in-stream; CSR via event). ----
    cudaStreamWaitEvent(0, evCSR, 0);
    agg2<<<(ND + 7) / 8, 256>>>(p_wd, DEG_WD, p_td, DEG_TD, NW + NT, out, ND);

    // ---- join. ----
    cudaStreamWaitEvent(0, evS2, 0);
}

// round 13
// speedup vs baseline: 1.3972x; 1.3972x over previous
#include <cuda_runtime.h>
#include <cuda_bf16.h>
#include <cstdint>

// Problem dimensions (fixed by the reference).
#define NW 50000
#define NT 2000
#define ND 50000
#define DO 128
#define DW 256
#define E_MAX 2200000   // total edges = 2.1M; padded

// Concatenated per-(relation,dst) counter layout.
constexpr int DEG_WW = 0;
constexpr int DEG_WT = NW;
constexpr int DEG_TT = NW + NT;
constexpr int DEG_WD = NW + 2 * NT;
constexpr int DEG_TD = NW + 2 * NT + ND;
constexpr int NDEG   = NW + 2 * NT + 2 * ND;   // 154000
constexpr int NSCAN  = (NDEG + 1023) / 1024;   // 151 scan blocks

// ---------------------------------------------------------------------------
// Scratch (static __device__ arrays — allocation-free per harness rules).
// ---------------------------------------------------------------------------
__device__ float g_Wh_ww[(size_t)NW * DO];
__device__ float g_Wh_wt[(size_t)NW * DO];
__device__ float g_Wh_wd[(size_t)NW * DO];
__device__ float g_Wh_td[(size_t)NT * DO];
__device__ float g_Wh_tt[(size_t)NT * DO];

__device__ int      g_cnt[NDEG];    // per-(rel,dst) degree
__device__ int      g_cur[NDEG];    // fill cursors for permute
__device__ int      g_off[NDEG];    // exclusive scan of g_cnt (global)
__device__ int      g_bsum[256];    // scan block sums
__device__ int      g_boff[256];    // scanned block sums

__device__ unsigned long long g_edge[E_MAX];  // packed (src | w<<32), dst-grouped

// Edge-set bundle for merged CSR kernels (passed by value).
struct ES {
    const int*   src[5];
    const int*   dst[5];
    const float* w[5];
    int          E[5];
    int          base[5];
};

// ---------------------------------------------------------------------------
// CSR build: zero counters -> merged histogram -> 3-phase scan -> merged
// permute (packed 8-byte edge payloads).
// ---------------------------------------------------------------------------
__global__ void zero_cnt() {
    int i = blockIdx.x * blockDim.x + threadIdx.x;
    if (i < NDEG) { g_cnt[i] = 0; g_cur[i] = 0; }
}

__global__ __launch_bounds__(256)
void hist_all(ES es, int total) {
    int i = blockIdx.x * blockDim.x + threadIdx.x;
    if (i >= total) return;
    int e = i;
#pragma unroll
    for (int r = 0; r < 5; r++) {
        if (e < es.E[r]) {
            atomicAdd(&g_cnt[es.base[r] + es.dst[r][e]], 1);
            return;
        }
        e -= es.E[r];
    }
}

__global__ __launch_bounds__(256)
void scan1() {
    __shared__ int sh[256];
    int t    = threadIdx.x;
    int base = blockIdx.x * 1024 + t * 4;
    int v[4];
#pragma unroll
    for (int j = 0; j < 4; j++)
        v[j] = (base + j < NDEG) ? g_cnt[base + j] : 0;
    int tsum = v[0] + v[1] + v[2] + v[3];
    sh[t] = tsum;
    __syncthreads();
    for (int d = 1; d < 256; d <<= 1) {
        int x = (t >= d) ? sh[t - d] : 0;
        __syncthreads();
        sh[t] += x;
        __syncthreads();
    }
    int run = sh[t] - tsum;
#pragma unroll
    for (int j = 0; j < 4; j++) {
        if (base + j < NDEG) g_off[base + j] = run;
        run += v[j];
    }
    if (t == 255) g_bsum[blockIdx.x] = sh[255];
}

__global__ __launch_bounds__(256)
void scan2() {
    __shared__ int sh[256];
    int t = threadIdx.x;
    int v = (t < NSCAN) ? g_bsum[t] : 0;
    sh[t] = v;
    __syncthreads();
    for (int d = 1; d < 256; d <<= 1) {
        int x = (t >= d) ? sh[t - d] : 0;
        __syncthreads();
        sh[t] += x;
        __syncthreads();
    }
    g_boff[t] = sh[t] - v;
}

__global__ __launch_bounds__(256)
void scan3() {
    int i = blockIdx.x * blockDim.x + threadIdx.x;
    if (i < NDEG) g_off[i] += g_boff[i >> 10];
}

__global__ __launch_bounds__(256)
void permute_all(ES es, int total) {
    int i = blockIdx.x * blockDim.x + threadIdx.x;
    if (i >= total) return;
    int e = i;
#pragma unroll
    for (int r = 0; r < 5; r++) {
        if (e < es.E[r]) {
            int d   = es.base[r] + es.dst[r][e];
            int pos = g_off[d] + atomicAdd(&g_cur[d], 1);
            unsigned long long p =
                (unsigned long long)(unsigned)es.src[r][e] |
                ((unsigned long long)__float_as_uint(es.w[r][e]) << 32);
            g_edge[pos] = p;
            return;
        }
        e -= es.E[r];
    }
}

// ---------------------------------------------------------------------------
// Split-BF16 tensor-core GEMM + bias: C[M x 128] = A[M x DIN] @ W[DIN x 128]+b
// mma.sync.m16n8k16.bf16 with 2-term split + 3-product compensation:
//   a = a_hi + a_lo (both bf16);  d += a_hi*b_hi + a_lo*b_hi + a_hi*b_lo
// -> O(2^-16) relative error, well under the 1e-3 gate; fp32 accumulate.
// K=16 per mma (2x tf32) -> mainloop mma count halves vs the tf32 version.
// BM=128, BN=128, BK=16, 256 threads = 8 warps (4 along M x 2 along N).
// Smem holds packed bf16x2 pairs (u32), row stride 12 (8 used + 4 pad):
// fragment LDS banks (row*12+tg)%32 are all distinct across the 8x4 lane map.
// blockIdx.y selects one of three (W, b, C) sets (all word GEMMs = 1 launch).
// ---------------------------------------------------------------------------
__device__ __forceinline__ void split_pack(float x0, float x1,
                                           uint32_t& hi, uint32_t& lo) {
    __nv_bfloat16 h0 = __float2bfloat16(x0);
    __nv_bfloat16 h1 = __float2bfloat16(x1);
    __nv_bfloat16 l0 = __float2bfloat16(x0 - __bfloat162float(h0));
    __nv_bfloat16 l1 = __float2bfloat16(x1 - __bfloat162float(h1));
    hi = (uint32_t)__bfloat16_as_ushort(h0) |
         ((uint32_t)__bfloat16_as_ushort(h1) << 16);
    lo = (uint32_t)__bfloat16_as_ushort(l0) |
         ((uint32_t)__bfloat16_as_ushort(l1) << 16);
}

__device__ __forceinline__ void mma_bf16(float* d, const uint32_t* a,
                                         const uint32_t* b) {
    asm volatile(
        "mma.sync.aligned.m16n8k16.row.col.f32.bf16.bf16.f32 "
        "{%0,%1,%2,%3}, {%4,%5,%6,%7}, {%8,%9}, {%0,%1,%2,%3};"
        : "+f"(d[0]), "+f"(d[1]), "+f"(d[2]), "+f"(d[3])
        : "r"(a[0]), "r"(a[1]), "r"(a[2]), "r"(a[3]), "r"(b[0]), "r"(b[1]));
}

template <int DIN>
__global__ __launch_bounds__(256)
void gemm_bf16(const float* __restrict__ A,
               const float* __restrict__ W0, const float* __restrict__ b0,
               float* __restrict__ C0,
               const float* __restrict__ W1, const float* __restrict__ b1,
               float* __restrict__ C1,
               const float* __restrict__ W2, const float* __restrict__ b2,
               float* __restrict__ C2, int M) {
    constexpr int S = 12;   // u32 row stride (8 kp used + 4 pad)
    __shared__ uint32_t As_hi[128 * S], As_lo[128 * S];   // [row][kp]
    __shared__ uint32_t Bs_hi[128 * S], Bs_lo[128 * S];   // [n][kp]

    const float* W    = (blockIdx.y == 0) ? W0 : (blockIdx.y == 1) ? W1 : W2;
    const float* bias = (blockIdx.y == 0) ? b0 : (blockIdx.y == 1) ? b1 : b2;
    float*       C    = (blockIdx.y == 0) ? C0 : (blockIdx.y == 1) ? C1 : C2;

    const int t    = threadIdx.x;
    const int m0   = blockIdx.x * 128;
    const int wid  = t >> 5;
    const int lane = t & 31;
    const int g    = lane >> 2;   // group id  (0..7)
    const int tg   = lane & 3;    // thread-in-group (0..3)
    const int m0w  = (wid & 3) * 32;   // warp M origin
    const int n0w  = (wid >> 2) * 64;  // warp N origin

    // Fill coordinates (both A and B fills: 128 rows/cols x 2 k-halves).
    const int fr  = t >> 1;          // row (A) / col n (B): 0..127
    const int fk8 = (t & 1) * 8;     // k offset 0 or 8
    const int fkp = fk8 >> 1;        // kp offset 0 or 4

    float acc[2][8][4];
#pragma unroll
    for (int mt = 0; mt < 2; mt++)
#pragma unroll
        for (int nt = 0; nt < 8; nt++)
#pragma unroll
            for (int j = 0; j < 4; j++) acc[mt][nt][j] = 0.0f;

    for (int k0 = 0; k0 < DIN; k0 += 16) {
        // ---- A fill: row fr, k = k0+fk8 .. +7, split+pack into 4 u32. ----
        {
            float v[8];
            if (m0 + fr < M) {
                const float* src = A + (size_t)(m0 + fr) * DIN + k0 + fk8;
                *(float4*)(v)     = *(const float4*)(src);
                *(float4*)(v + 4) = *(const float4*)(src + 4);
            } else {
#pragma unroll
                for (int j = 0; j < 8; j++) v[j] = 0.0f;
            }
#pragma unroll
            for (int j = 0; j < 4; j++) {
                uint32_t hi, lo;
                split_pack(v[2 * j], v[2 * j + 1], hi, lo);
                As_hi[fr * S + fkp + j] = hi;
                As_lo[fr * S + fkp + j] = lo;
            }
        }
        // ---- B fill: col n = fr, k = k0+fk8 .. +7 (8 strided scalars). ----
        {
            float v[8];
#pragma unroll
            for (int j = 0; j < 8; j++)
                v[j] = W[(size_t)(k0 + fk8 + j) * DO + fr];
#pragma unroll
            for (int j = 0; j < 4; j++) {
                uint32_t hi, lo;
                split_pack(v[2 * j], v[2 * j + 1], hi, lo);
                Bs_hi[fr * S + fkp + j] = hi;
                Bs_lo[fr * S + fkp + j] = lo;
            }
        }
        __syncthreads();

        // ---- One m16n8k16 step covers the whole 16-wide k tile. ----
        uint32_t a_hi[2][4], a_lo[2][4];
#pragma unroll
        for (int mt = 0; mt < 2; mt++) {
            int r0 = (m0w + mt * 16 + g) * S;
            int r1 = (m0w + mt * 16 + g + 8) * S;
            a_hi[mt][0] = As_hi[r0 + tg];
            a_hi[mt][1] = As_hi[r1 + tg];
            a_hi[mt][2] = As_hi[r0 + tg + 4];
            a_hi[mt][3] = As_hi[r1 + tg + 4];
            a_lo[mt][0] = As_lo[r0 + tg];
            a_lo[mt][1] = As_lo[r1 + tg];
            a_lo[mt][2] = As_lo[r0 + tg + 4];
            a_lo[mt][3] = As_lo[r1 + tg + 4];
        }
#pragma unroll
        for (int nt = 0; nt < 8; nt++) {
            int nb = (n0w + nt * 8 + g) * S;
            uint32_t b_hi[2], b_lo[2];
            b_hi[0] = Bs_hi[nb + tg];
            b_hi[1] = Bs_hi[nb + tg + 4];
            b_lo[0] = Bs_lo[nb + tg];
            b_lo[1] = Bs_lo[nb + tg + 4];
#pragma unroll
            for (int mt = 0; mt < 2; mt++) {
                mma_bf16(acc[mt][nt], a_hi[mt], b_hi);
                mma_bf16(acc[mt][nt], a_lo[mt], b_hi);
                mma_bf16(acc[mt][nt], a_hi[mt], b_lo);
            }
        }
        __syncthreads();
    }

    // Epilogue: bias + store.
#pragma unroll
    for (int nt = 0; nt < 8; nt++) {
        int col = n0w + nt * 8 + 2 * tg;
        float bx = bias[col];
        float by = bias[col + 1];
#pragma unroll
        for (int mt = 0; mt < 2; mt++) {
            int mr = m0 + m0w + mt * 16 + g;
            if (mr < M) {
                float2 o = make_float2(acc[mt][nt][0] + bx,
                                       acc[mt][nt][1] + by);
                *(float2*)(C + (size_t)mr * DO + col) = o;
            }
            if (mr + 8 < M) {
                float2 o = make_float2(acc[mt][nt][2] + bx,
                                       acc[mt][nt][3] + by);
                *(float2*)(C + (size_t)(mr + 8) * DO + col) = o;
            }
        }
    }
}

// ---------------------------------------------------------------------------
// Aggregation (CSR, atomic-free): ONE WARP per dst row, lane owns a float4
// column slice -> one LDG.128 per lane per edge. 2x-unrolled edge loop (the
// R10 configuration; 4x regressed). Mean + cross-etype sum + coalesced store.
// ---------------------------------------------------------------------------
__device__ __forceinline__ float4 mean_row_w(const float* __restrict__ Wh,
                                             int cnt_base, int row, int lane) {
    int beg = g_off[cnt_base + row];
    int deg = g_cnt[cnt_base + row];
    float4 a0 = make_float4(0.f, 0.f, 0.f, 0.f);
    float4 a1 = make_float4(0.f, 0.f, 0.f, 0.f);
    int e = 0;
    for (; e + 2 <= deg; e += 2) {
        unsigned long long pA = g_edge[beg + e];
        unsigned long long pB = g_edge[beg + e + 1];
        int   sA = (int)(unsigned)pA;
        int   sB = (int)(unsigned)pB;
        float wA = __uint_as_float((unsigned)(pA >> 32));
        float wB = __uint_as_float((unsigned)(pB >> 32));
        float4 vA = *(const float4*)(Wh + (size_t)sA * DO + lane * 4);
        float4 vB = *(const float4*)(Wh + (size_t)sB * DO + lane * 4);
        a0.x += wA * vA.x; a0.y += wA * vA.y;
        a0.z += wA * vA.z; a0.w += wA * vA.w;
        a1.x += wB * vB.x; a1.y += wB * vB.y;
        a1.z += wB * vB.z; a1.w += wB * vB.w;
    }
    if (e < deg) {
        unsigned long long p = g_edge[beg + e];
        int   s = (int)(unsigned)p;
        float w = __uint_as_float((unsigned)(p >> 32));
        float4 v = *(const float4*)(Wh + (size_t)s * DO + lane * 4);
        a0.x += w * v.x; a0.y += w * v.y;
        a0.z += w * v.z; a0.w += w * v.w;
    }
    float inv = (deg > 0) ? 1.0f / (float)deg : 0.0f;
    return make_float4((a0.x + a1.x) * inv, (a0.y + a1.y) * inv,
                       (a0.z + a1.z) * inv, (a0.w + a1.w) * inv);
}

__global__ __launch_bounds__(256)
void agg1(const float* __restrict__ Wh, int cnt_base, int out_row0,
          float* __restrict__ out, int nrows) {
    int row  = blockIdx.x * 8 + (threadIdx.x >> 5);
    int lane = threadIdx.x & 31;
    if (row >= nrows) return;
    float4 r = mean_row_w(Wh, cnt_base, row, lane);
    *(float4*)(out + (size_t)(out_row0 + row) * DO + lane * 4) = r;
}

__global__ __launch_bounds__(256)
void agg2(const float* __restrict__ WhA, int baseA,
          const float* __restrict__ WhB, int baseB, int out_row0,
          float* __restrict__ out, int nrows) {
    int row  = blockIdx.x * 8 + (threadIdx.x >> 5);
    int lane = threadIdx.x & 31;
    if (row >= nrows) return;
    float4 rA = mean_row_w(WhA, baseA, row, lane);
    float4 rB = mean_row_w(WhB, baseB, row, lane);
    float4 o  = make_float4(rA.x + rB.x, rA.y + rB.y,
                            rA.z + rB.z, rA.w + rB.w);
    *(float4*)(out + (size_t)(out_row0 + row) * DO + lane * 4) = o;
}

// ---------------------------------------------------------------------------
// Host entry.
// Input order (metadata): 0 feat_word, 1 feat_topic,
//   2-4 ww(src,dst,w), 5-7 wt, 8-10 wd, 11-13 td, 14-16 tt,
//   17/18 W_ww/b_ww, 19/20 W_wt/b_wt, 21/22 W_wd/b_wd, 23/24 W_td/b_td,
//   25/26 W_tt/b_tt
//
// DAG (capture-legal fork), R10 topology:
//   legacy: evFork -> G_words(y=3, evGw) -> G_topics(y=2, evGt)
//           -> [evCSR] agg_doc -> [evS2] join
//   s2:     [evFork] zero_cnt -> hist_all -> scan x3 -> permute_all (evCSR)
//           -> [evGw] agg_word -> [evGt] agg_topic (evS2)
// ---------------------------------------------------------------------------
extern "C" void kernel_launch(void* const* d_in, const int* in_sizes, int n_in,
                              void* d_out, int out_size) {
    static cudaStream_t s2 = nullptr;
    static cudaEvent_t  evFork, evCSR, evGw, evGt, evS2;
    if (s2 == nullptr) {
        cudaStreamCreateWithFlags(&s2, cudaStreamNonBlocking);
        cudaEventCreateWithFlags(&evFork, cudaEventDisableTiming);
        cudaEventCreateWithFlags(&evCSR,  cudaEventDisableTiming);
        cudaEventCreateWithFlags(&evGw,   cudaEventDisableTiming);
        cudaEventCreateWithFlags(&evGt,   cudaEventDisableTiming);
        cudaEventCreateWithFlags(&evS2,   cudaEventDisableTiming);
    }

    const float* feat_word  = (const float*)d_in[0];
    const float* feat_topic = (const float*)d_in[1];

    // Edge sets in CSR order: ww, wt, tt, wd, td.
    ES es;
    es.src[0] = (const int*)d_in[2];  es.dst[0] = (const int*)d_in[3];
    es.w[0] = (const float*)d_in[4];  es.E[0] = in_sizes[2];  es.base[0] = DEG_WW;
    es.src[1] = (const int*)d_in[5];  es.dst[1] = (const int*)d_in[6];
    es.w[1] = (const float*)d_in[7];  es.E[1] = in_sizes[5];  es.base[1] = DEG_WT;
    es.src[2] = (const int*)d_in[14]; es.dst[2] = (const int*)d_in[15];
    es.w[2] = (const float*)d_in[16]; es.E[2] = in_sizes[14]; es.base[2] = DEG_TT;
    es.src[3] = (const int*)d_in[8];  es.dst[3] = (const int*)d_in[9];
    es.w[3] = (const float*)d_in[10]; es.E[3] = in_sizes[8];  es.base[3] = DEG_WD;
    es.src[4] = (const int*)d_in[11]; es.dst[4] = (const int*)d_in[12];
    es.w[4] = (const float*)d_in[13]; es.E[4] = in_sizes[11]; es.base[4] = DEG_TD;
    int totalE = es.E[0] + es.E[1] + es.E[2] + es.E[3] + es.E[4];

    const float* W_ww = (const float*)d_in[17]; const float* b_ww = (const float*)d_in[18];
    const float* W_wt = (const float*)d_in[19]; const float* b_wt = (const float*)d_in[20];
    const float* W_wd = (const float*)d_in[21]; const float* b_wd = (const float*)d_in[22];
    const float* W_td = (const float*)d_in[23]; const float* b_td = (const float*)d_in[24];
    const float* W_tt = (const float*)d_in[25]; const float* b_tt = (const float*)d_in[26];

    float* out = (float*)d_out;

    float* p_ww; cudaGetSymbolAddress((void**)&p_ww, g_Wh_ww);
    float* p_wt; cudaGetSymbolAddress((void**)&p_wt, g_Wh_wt);
    float* p_wd; cudaGetSymbolAddress((void**)&p_wd, g_Wh_wd);
    float* p_td; cudaGetSymbolAddress((void**)&p_td, g_Wh_td);
    float* p_tt; cudaGetSymbolAddress((void**)&p_tt, g_Wh_tt);

    // ---- Fork s2 from the capture (legacy) stream. ----
    cudaEventRecord(evFork, 0);
    cudaStreamWaitEvent(s2, evFork, 0);

    // ---- s2: CSR build (independent of GEMMs). ----
    zero_cnt<<<(NDEG + 255) / 256, 256, 0, s2>>>();
    hist_all<<<(totalE + 255) / 256, 256, 0, s2>>>(es, totalE);
    scan1<<<NSCAN, 256, 0, s2>>>();
    scan2<<<1, 256, 0, s2>>>();
    scan3<<<(NDEG + 255) / 256, 256, 0, s2>>>();
    permute_all<<<(totalE + 255) / 256, 256, 0, s2>>>(es, totalE);
    cudaEventRecord(evCSR, s2);

    // ---- legacy: projections (tensor cores, split-bf16). ----
    {
        int gw = (NW + 127) / 128;   // 391 -> y=3: 1173 CTAs, ~4 full waves
        gemm_bf16<DW><<<dim3(gw, 3), 256>>>(feat_word,
                                            W_ww, b_ww, p_ww,
                                            W_wt, b_wt, p_wt,
                                            W_wd, b_wd, p_wd, NW);
        cudaEventRecord(evGw, 0);
        int gt = (NT + 127) / 128;   // 16
        gemm_bf16<128><<<dim3(gt, 2), 256>>>(feat_topic,
                                             W_tt, b_tt, p_tt,
                                             W_td, b_td, p_td,
                                             W_td, b_td, p_td, NT);
        cudaEventRecord(evGt, 0);
    }

    // ---- s2: aggregates as dependencies resolve (CSR is in-stream). ----
    cudaStreamWaitEvent(s2, evGw, 0);
    agg1<<<(NW + 7) / 8, 256, 0, s2>>>(p_ww, DEG_WW, 0, out, NW);
    cudaStreamWaitEvent(s2, evGt, 0);
    agg2<<<(NT + 7) / 8, 256, 0, s2>>>(p_wt, DEG_WT, p_tt, DEG_TT, NW, out, NT);
    cudaEventRecord(evS2, s2);

    // ---- legacy: doc aggregate (GEMMs in-stream; CSR via event). ----
    cudaStreamWaitEvent(0, evCSR, 0);
    agg2<<<(ND + 7) / 8, 256>>>(p_wd, DEG_WD, p_td, DEG_TD, NW + NT, out, ND);

    // ---- join. ----
    cudaStreamWaitEvent(0, evS2, 0);
}